// round 6
// baseline (speedup 1.0000x reference)
#include <cuda_runtime.h>
#include <cstdint>

#define BOND_CUTOFF 3.6f
#define N_MAX 8192

// Static scratch: packed positions (x,y,z,pad). 8192 * 16 B = 128 KB.
__device__ float4 g_pos[N_MAX];

// ---------------------------------------------------------------------------
// Kernel 1: pack stride-7 input into contiguous float4 array.
// ---------------------------------------------------------------------------
__global__ void pack_pos_kernel(const float* __restrict__ x, int n) {
    int j = blockIdx.x * blockDim.x + threadIdx.x;
    if (j < n) {
        const float* p = x + (size_t)j * 7;
        g_pos[j] = make_float4(p[0], p[1], p[2], 0.0f);
    }
}

// ---------------------------------------------------------------------------
// Kernel 2: thresholded L1 distance matrix.
// Block: 128 threads. Tile: TI=32 rows x TJ=512 cols. Grid 16 x 256 = 4096.
// Same block count and bytes/block (64KB) as the measured-best round-1
// config, but the load:store L1-wavefront ratio drops 50% -> 37.5%:
//   - 4 cols/thread loaded once, amortized over 32 rows (2x round 1)
//   - one coalesced float4 store per thread per row (512B/warp contiguous)
// ---------------------------------------------------------------------------
#define TI 32
#define TJ 512

__global__ __launch_bounds__(128, 16)
void graph_kernel(float* __restrict__ out, int n) {
    const int t  = threadIdx.x;
    const int j0 = blockIdx.x * TJ + t * 4;   // first of this thread's 4 cols
    const int i0 = blockIdx.y * TI;

    // Coalesced packed loads (LDG.128, 4 wavefronts each).
    float4 c0 = g_pos[j0 + 0];
    float4 c1 = g_pos[j0 + 1];
    float4 c2 = g_pos[j0 + 2];
    float4 c3 = g_pos[j0 + 3];

    float* orow = out + (size_t)i0 * n + j0;

#pragma unroll
    for (int r = 0; r < TI; r++) {
        // Uniform broadcast load (1 wavefront, L1 hit).
        float4 pi = g_pos[i0 + r];

        float4 res;
        {
            float d0 = (fabsf(pi.x - c0.x) + fabsf(pi.y - c0.y)) + fabsf(pi.z - c0.z);
            float d1 = (fabsf(pi.x - c1.x) + fabsf(pi.y - c1.y)) + fabsf(pi.z - c1.z);
            float d2 = (fabsf(pi.x - c2.x) + fabsf(pi.y - c2.y)) + fabsf(pi.z - c2.z);
            float d3 = (fabsf(pi.x - c3.x) + fabsf(pi.y - c3.y)) + fabsf(pi.z - c3.z);
            res.x = (d0 <= BOND_CUTOFF) ? 1.0f : 0.0f;
            res.y = (d1 <= BOND_CUTOFF) ? 1.0f : 0.0f;
            res.z = (d2 <= BOND_CUTOFF) ? 1.0f : 0.0f;
            res.w = (d3 <= BOND_CUTOFF) ? 1.0f : 0.0f;
        }

        *reinterpret_cast<float4*>(orow) = res;
        orow += n;
    }
}

// ---------------------------------------------------------------------------
// Fallback for shapes that don't tile evenly (defensive; N=8192 does).
// ---------------------------------------------------------------------------
__global__ void graph_kernel_generic(float* __restrict__ out, int n) {
    int j = blockIdx.x * blockDim.x + threadIdx.x;
    int i = blockIdx.y;
    if (i < n && j < n) {
        float4 pi = g_pos[i];
        float4 pj = g_pos[j];
        float d = (fabsf(pi.x - pj.x) + fabsf(pi.y - pj.y)) + fabsf(pi.z - pj.z);
        out[(size_t)i * n + j] = (d <= BOND_CUTOFF) ? 1.0f : 0.0f;
    }
}

extern "C" void kernel_launch(void* const* d_in, const int* in_sizes, int n_in,
                              void* d_out, int out_size) {
    const float* x = (const float*)d_in[0];
    int n = in_sizes[0] / 7;
    float* out = (float*)d_out;

    pack_pos_kernel<<<(n + 255) / 256, 256>>>(x, n);

    if (n > 0 && n <= N_MAX && (n % TJ) == 0 && (n % TI) == 0) {
        dim3 grid(n / TJ, n / TI);
        graph_kernel<<<grid, 128>>>(out, n);
    } else {
        dim3 grid((n + 255) / 256, n);
        graph_kernel_generic<<<grid, 256>>>(out, n);
    }
}

// round 7
// speedup vs baseline: 1.0378x; 1.0378x over previous
#include <cuda_runtime.h>
#include <cstdint>

#define BOND_CUTOFF 3.6f
#define N_MAX 8192

// Static scratch: packed positions (x,y,z,pad). 8192 * 16 B = 128 KB.
__device__ float4 g_pos[N_MAX];

// ---------------------------------------------------------------------------
// Kernel 1: pack stride-7 input into contiguous float4 array.
// ---------------------------------------------------------------------------
__global__ void pack_pos_kernel(const float* __restrict__ x, int n) {
    int j = blockIdx.x * blockDim.x + threadIdx.x;
    if (j < n) {
        const float* p = x + (size_t)j * 7;
        g_pos[j] = make_float4(p[0], p[1], p[2], 0.0f);
    }
}

// ---------------------------------------------------------------------------
// Kernel 2: thresholded L1 distance matrix.
// EXACT round-1 structure (the measured best: 42.9us @ DRAM 60%):
//   Block: 256 threads. Tile: TI=16 rows x TJ=1024 cols. Grid 8 x 512.
//   4 cols/thread in registers (coalesced LDG.128 from packed array),
//   16 rows, one coalesced float4 store per row.
// Single change under test: write-through stores (STG.WT) -> skip the L2
// dirty-line allocate/evict lifecycle for the write-once 268MB output.
// ---------------------------------------------------------------------------
#define TI 16
#define TJ 1024

__global__ __launch_bounds__(256, 8)
void graph_kernel(float* __restrict__ out, int n) {
    const int t  = threadIdx.x;
    const int j0 = blockIdx.x * TJ + t * 4;   // first of this thread's 4 cols
    const int i0 = blockIdx.y * TI;

    // Coalesced packed loads (L1-resident after first wave).
    float4 c0 = g_pos[j0 + 0];
    float4 c1 = g_pos[j0 + 1];
    float4 c2 = g_pos[j0 + 2];
    float4 c3 = g_pos[j0 + 3];

    float* orow = out + (size_t)i0 * n + j0;

#pragma unroll
    for (int r = 0; r < TI; r++) {
        // Uniform broadcast load (1 wavefront, L1 hit).
        float4 pi = g_pos[i0 + r];

        float4 res;
        {
            float d0 = (fabsf(pi.x - c0.x) + fabsf(pi.y - c0.y)) + fabsf(pi.z - c0.z);
            float d1 = (fabsf(pi.x - c1.x) + fabsf(pi.y - c1.y)) + fabsf(pi.z - c1.z);
            float d2 = (fabsf(pi.x - c2.x) + fabsf(pi.y - c2.y)) + fabsf(pi.z - c2.z);
            float d3 = (fabsf(pi.x - c3.x) + fabsf(pi.y - c3.y)) + fabsf(pi.z - c3.z);
            res.x = (d0 <= BOND_CUTOFF) ? 1.0f : 0.0f;
            res.y = (d1 <= BOND_CUTOFF) ? 1.0f : 0.0f;
            res.z = (d2 <= BOND_CUTOFF) ? 1.0f : 0.0f;
            res.w = (d3 <= BOND_CUTOFF) ? 1.0f : 0.0f;
        }

        // Write-through: output is write-once, never re-read.
        __stwt(reinterpret_cast<float4*>(orow), res);
        orow += n;
    }
}

// ---------------------------------------------------------------------------
// Fallback for shapes that don't tile evenly (defensive; N=8192 does).
// ---------------------------------------------------------------------------
__global__ void graph_kernel_generic(float* __restrict__ out, int n) {
    int j = blockIdx.x * blockDim.x + threadIdx.x;
    int i = blockIdx.y;
    if (i < n && j < n) {
        float4 pi = g_pos[i];
        float4 pj = g_pos[j];
        float d = (fabsf(pi.x - pj.x) + fabsf(pi.y - pj.y)) + fabsf(pi.z - pj.z);
        out[(size_t)i * n + j] = (d <= BOND_CUTOFF) ? 1.0f : 0.0f;
    }
}

extern "C" void kernel_launch(void* const* d_in, const int* in_sizes, int n_in,
                              void* d_out, int out_size) {
    const float* x = (const float*)d_in[0];
    int n = in_sizes[0] / 7;
    float* out = (float*)d_out;

    pack_pos_kernel<<<(n + 255) / 256, 256>>>(x, n);

    if (n > 0 && n <= N_MAX && (n % TJ) == 0 && (n % TI) == 0) {
        dim3 grid(n / TJ, n / TI);
        graph_kernel<<<grid, 256>>>(out, n);
    } else {
        dim3 grid((n + 255) / 256, n);
        graph_kernel_generic<<<grid, 256>>>(out, n);
    }
}

// round 8
// speedup vs baseline: 1.0435x; 1.0054x over previous
#include <cuda_runtime.h>
#include <cstdint>

#define BOND_CUTOFF 3.6f
#define N_MAX 8192

// Static scratch: packed positions (x,y,z,pad). 8192 * 16 B = 128 KB.
__device__ float4 g_pos[N_MAX];

// ---------------------------------------------------------------------------
// Kernel 1: pack stride-7 input into contiguous float4 array.
// ---------------------------------------------------------------------------
__global__ void pack_pos_kernel(const float* __restrict__ x, int n) {
    int j = blockIdx.x * blockDim.x + threadIdx.x;
    if (j < n) {
        const float* p = x + (size_t)j * 7;
        g_pos[j] = make_float4(p[0], p[1], p[2], 0.0f);
    }
}

// ---------------------------------------------------------------------------
// Kernel 2: thresholded L1 distance matrix.
// Round-1 tiling (measured best): 256 threads, TI=16 x TJ=1024, grid 8x512.
// Change under test: row positions broadcast via warp SHUFFLE instead of
// per-iteration uniform L1 loads. Lane (t&15) holds row i0+(t&15) in regs
// (one coalesced LDG.128 covering 2 lines per warp); the inner loop uses
// 3 SHFL.IDX per row. This removes 128 L1 wavefronts/block from the path
// shared with the 512 store wavefronts -> more L1 slots for the write drain.
// ---------------------------------------------------------------------------
#define TI 16
#define TJ 1024

__global__ __launch_bounds__(256, 8)
void graph_kernel(float* __restrict__ out, int n) {
    const int t  = threadIdx.x;
    const int j0 = blockIdx.x * TJ + t * 4;   // first of this thread's 4 cols
    const int i0 = blockIdx.y * TI;

    // Column positions (coalesced, L1-resident after first wave).
    float4 c0 = g_pos[j0 + 0];
    float4 c1 = g_pos[j0 + 1];
    float4 c2 = g_pos[j0 + 2];
    float4 c3 = g_pos[j0 + 3];

    // Each lane holds one of the 16 row positions (lanes 16-31 duplicate).
    float4 rp = g_pos[i0 + (t & 15)];
    float rx = rp.x, ry = rp.y, rz = rp.z;

    float* orow = out + (size_t)i0 * n + j0;

#pragma unroll
    for (int r = 0; r < TI; r++) {
        // Row broadcast via shuffle: no L1 traffic.
        float px = __shfl_sync(0xffffffffu, rx, r);
        float py = __shfl_sync(0xffffffffu, ry, r);
        float pz = __shfl_sync(0xffffffffu, rz, r);

        float4 res;
        {
            float d0 = (fabsf(px - c0.x) + fabsf(py - c0.y)) + fabsf(pz - c0.z);
            float d1 = (fabsf(px - c1.x) + fabsf(py - c1.y)) + fabsf(pz - c1.z);
            float d2 = (fabsf(px - c2.x) + fabsf(py - c2.y)) + fabsf(pz - c2.z);
            float d3 = (fabsf(px - c3.x) + fabsf(py - c3.y)) + fabsf(pz - c3.z);
            res.x = (d0 <= BOND_CUTOFF) ? 1.0f : 0.0f;
            res.y = (d1 <= BOND_CUTOFF) ? 1.0f : 0.0f;
            res.z = (d2 <= BOND_CUTOFF) ? 1.0f : 0.0f;
            res.w = (d3 <= BOND_CUTOFF) ? 1.0f : 0.0f;
        }

        *reinterpret_cast<float4*>(orow) = res;
        orow += n;
    }
}

// ---------------------------------------------------------------------------
// Fallback for shapes that don't tile evenly (defensive; N=8192 does).
// ---------------------------------------------------------------------------
__global__ void graph_kernel_generic(float* __restrict__ out, int n) {
    int j = blockIdx.x * blockDim.x + threadIdx.x;
    int i = blockIdx.y;
    if (i < n && j < n) {
        float4 pi = g_pos[i];
        float4 pj = g_pos[j];
        float d = (fabsf(pi.x - pj.x) + fabsf(pi.y - pj.y)) + fabsf(pi.z - pj.z);
        out[(size_t)i * n + j] = (d <= BOND_CUTOFF) ? 1.0f : 0.0f;
    }
}

extern "C" void kernel_launch(void* const* d_in, const int* in_sizes, int n_in,
                              void* d_out, int out_size) {
    const float* x = (const float*)d_in[0];
    int n = in_sizes[0] / 7;
    float* out = (float*)d_out;

    pack_pos_kernel<<<(n + 255) / 256, 256>>>(x, n);

    if (n > 0 && n <= N_MAX && (n % TJ) == 0 && (n % TI) == 0) {
        dim3 grid(n / TJ, n / TI);
        graph_kernel<<<grid, 256>>>(out, n);
    } else {
        dim3 grid((n + 255) / 256, n);
        graph_kernel_generic<<<grid, 256>>>(out, n);
    }
}